// round 1
// baseline (speedup 1.0000x reference)
#include <cuda_runtime.h>
#include <cuda_bf16.h>
#include <stdint.h>

#define BB 4
#define NN 2048
#define MM 8192
#define DD 128
#define SS 1024   // NUM_SEGMENTS

// ---------------- scratch (static __device__, no allocation) ----------------
__device__ float g_seg_sum[BB * SS * DD];  // 2 MB: per-(b,seg) running sums
__device__ int   g_cnt[BB * SS];           // per-(b,seg) row counts
__device__ int   g_off[BB * SS];           // exclusive prefix (within batch)
__device__ int   g_pos[BB * SS];           // running fill cursor
__device__ int   g_rows[BB * MM];          // row ids grouped by segment

// ---------------- 1) zero counts ----------------
__global__ void k_zero_cnt() {
    int i = blockIdx.x * blockDim.x + threadIdx.x;
    if (i < BB * SS) g_cnt[i] = 0;
}

// ---------------- 2) histogram of source segment ids ----------------
__global__ void k_hist(const int* __restrict__ idx_src) {
    int i = blockIdx.x * blockDim.x + threadIdx.x;   // i = b*MM + m
    if (i >= BB * MM) return;
    int b = i / MM;
    int s = idx_src[i];
    atomicAdd(&g_cnt[b * SS + s], 1);
}

// ---------------- 3) per-batch exclusive scan over 1024 counts ----------------
__global__ void k_scan() {
    __shared__ int sh[SS];
    int b = blockIdx.x;
    int t = threadIdx.x;                 // 0..1023
    int v = g_cnt[b * SS + t];
    sh[t] = v;
    __syncthreads();
    #pragma unroll
    for (int d = 1; d < SS; d <<= 1) {
        int add = (t >= d) ? sh[t - d] : 0;
        __syncthreads();
        sh[t] += add;
        __syncthreads();
    }
    int excl = sh[t] - v;                // exclusive prefix within batch
    g_off[b * SS + t] = excl;
    g_pos[b * SS + t] = excl;
}

// ---------------- 4) scatter row ids into segment-grouped order ----------------
__global__ void k_scatter(const int* __restrict__ idx_src) {
    int i = blockIdx.x * blockDim.x + threadIdx.x;   // i = b*MM + m
    if (i >= BB * MM) return;
    int b = i / MM;
    int m = i - b * MM;
    int s = idx_src[i];
    int p = atomicAdd(&g_pos[b * SS + s], 1);
    g_rows[b * MM + p] = m;
}

// ---------------- 5) per-(b,segment) sum: one warp per segment ----------------
__global__ void k_segsum(const float* __restrict__ src) {
    int warp = (blockIdx.x * blockDim.x + threadIdx.x) >> 5;  // 0..BB*SS-1
    int lane = threadIdx.x & 31;
    if (warp >= BB * SS) return;
    int b = warp / SS;
    int cnt = g_cnt[warp];
    int off = g_off[warp];
    const int* rows = g_rows + b * MM + off;

    float4 acc = make_float4(0.f, 0.f, 0.f, 0.f);
    for (int r = 0; r < cnt; r++) {
        int m = rows[r];                                  // broadcast load
        const float4* row = (const float4*)(src + ((size_t)(b * MM + m)) * DD);
        float4 v = row[lane];                             // coalesced 512B/row
        acc.x += v.x; acc.y += v.y; acc.z += v.z; acc.w += v.w;
    }
    ((float4*)(g_seg_sum + (size_t)warp * DD))[lane] = acc;
}

// ---------------- 6) per-(b,target) gather + divide: one warp per target ----------------
__global__ void k_gather(const int* __restrict__ idx_tgt, float* __restrict__ out) {
    int warp = (blockIdx.x * blockDim.x + threadIdx.x) >> 5;  // 0..BB*NN-1
    int lane = threadIdx.x & 31;
    if (warp >= BB * NN) return;
    int b = warp / NN;
    int s = idx_tgt[warp];
    int slot = b * SS + s;
    float inv = 1.0f / ((float)g_cnt[slot] + 1e-10f);
    float4 v = ((const float4*)(g_seg_sum + (size_t)slot * DD))[lane];
    v.x *= inv; v.y *= inv; v.z *= inv; v.w *= inv;
    ((float4*)(out + (size_t)warp * DD))[lane] = v;
}

// ---------------- launch ----------------
extern "C" void kernel_launch(void* const* d_in, const int* in_sizes, int n_in,
                              void* d_out, int out_size) {
    const int*   idx_tgt = (const int*)d_in[0];    // [B, N, 1]
    const int*   idx_src = (const int*)d_in[1];    // [B, M, 1]
    const float* src     = (const float*)d_in[2];  // [B, M, D]
    float*       out     = (float*)d_out;          // [B, N, D]

    k_zero_cnt<<<(BB * SS + 1023) / 1024, 1024>>>();
    k_hist   <<<(BB * MM + 255) / 256, 256>>>(idx_src);
    k_scan   <<<BB, SS>>>();
    k_scatter<<<(BB * MM + 255) / 256, 256>>>(idx_src);
    k_segsum <<<(BB * SS * 32 + 255) / 256, 256>>>(src);
    k_gather <<<(BB * NN * 32 + 255) / 256, 256>>>(idx_tgt, out);
}